// round 4
// baseline (speedup 1.0000x reference)
#include <cuda_runtime.h>
#include <math.h>

#define BB 4
#define LL 2048
#define DD 32
#define TT 21   // NUM_TYPES + 1

// out layout (f32):
//   scores  : [B, L, L]   at offset 0
//   hidden  : [B, L, 2D]  at offset B*L*L
//   t_diff  : [B, L, L]   at offset B*L*L + B*L*2D
#define SCORES_OFF  ((size_t)0)
#define HID_OFF     ((size_t)BB * LL * LL)
#define TD_OFF      (HID_OFF + (size_t)BB * LL * 2 * DD)

// div_term[h] = exp(2h * (-ln(10000)/32)) = 10^(-h/4), hardcoded
__device__ __constant__ float c_divt[16] = {
    1.0f,
    0.5623413251903491f,
    0.31622776601683794f,
    0.17782794100389226f,
    0.1f,
    0.05623413251903491f,
    0.031622776601683791f,
    0.017782794100389228f,
    0.01f,
    0.005623413251903491f,
    0.0031622776601683794f,
    0.0017782794100389228f,
    0.001f,
    0.0005623413251903491f,
    0.00031622776601683794f,
    0.00017782794100389227f
};

// One block per (b, i) row. 512 threads; each thread handles one float4 of j.
// Warp 0 (21 lanes) recomputes the 21-entry (gs, dn) table row for type_i.
__global__ __launch_bounds__(512)
void fused_kernel(const int*   __restrict__ event_type,
                  const float* __restrict__ event_time,
                  const float* __restrict__ Wt,
                  const float* __restrict__ type_table,
                  const float* __restrict__ w_g, const float* __restrict__ b_g,
                  const float* __restrict__ w_s, const float* __restrict__ b_s,
                  const float* __restrict__ w_d, const float* __restrict__ b_d,
                  float* __restrict__ out)
{
    const int bi  = blockIdx.x;          // b * L + i
    const int b   = bi >> 11;            // / 2048
    const int i   = bi & (LL - 1);
    const int tid = threadIdx.x;

    __shared__ float2 sh[TT];            // (gs, dn) per type_j

    const int   tyi = event_type[bi];    // broadcast load
    const float t_i = event_time[bi];    // broadcast load

    // ---- per-block table row (warp 0, lanes 0..20) ----
    if (tid < TT) {
        const float4* ej = (const float4*)(type_table + tid * DD);
        const float4* ei = (const float4*)(type_table + tyi * DD);
        const float4* wg = (const float4*)w_g;   // [0..7] = w[:32], [8..15] = w[32:]
        const float4* ws = (const float4*)w_s;
        const float4* wd = (const float4*)w_d;
        float g = *b_g, s = *b_s, d = *b_d;
#pragma unroll
        for (int q = 0; q < 8; q++) {
            float4 aj = ej[q], ai = ei[q];
            float4 g0 = wg[q], g1 = wg[q + 8];
            float4 s0 = ws[q], s1 = ws[q + 8];
            float4 d0 = wd[q], d1 = wd[q + 8];
            g = fmaf(aj.x, g0.x, fmaf(aj.y, g0.y, fmaf(aj.z, g0.z, fmaf(aj.w, g0.w, g))));
            g = fmaf(ai.x, g1.x, fmaf(ai.y, g1.y, fmaf(ai.z, g1.z, fmaf(ai.w, g1.w, g))));
            s = fmaf(aj.x, s0.x, fmaf(aj.y, s0.y, fmaf(aj.z, s0.z, fmaf(aj.w, s0.w, s))));
            s = fmaf(ai.x, s1.x, fmaf(ai.y, s1.y, fmaf(ai.z, s1.z, fmaf(ai.w, s1.w, s))));
            d = fmaf(aj.x, d0.x, fmaf(aj.y, d0.y, fmaf(aj.z, d0.z, fmaf(aj.w, d0.w, d))));
            d = fmaf(ai.x, d1.x, fmaf(ai.y, d1.y, fmaf(ai.z, d1.z, fmaf(ai.w, d1.w, d))));
        }
        // sigmoid(g) * softplus(s), -softplus(d)  (stable forms, fast intrinsics)
        float sig = 1.0f / (1.0f + __expf(-g));
        float sps = fmaxf(s, 0.0f) + __logf(1.0f + __expf(-fabsf(s)));
        float spd = fmaxf(d, 0.0f) + __logf(1.0f + __expf(-fabsf(d)));
        sh[tid] = make_float2(sig * sps, -spd);
    }

    // ---- fused hidden_vector row (warps 2-3, lanes map to the 64 outputs) ----
    if (tid >= 64 && tid < 128) {
        const int h2 = tid - 64;
        float v;
        if (h2 < DD) {
            int h = h2 & 15;
            float arg = fmaf((float)i, c_divt[h], t_i * Wt[h]);
            v = (h2 < 16) ? sinf(arg) : cosf(arg);
        } else {
            v = type_table[tyi * DD + (h2 - DD)];
        }
        out[HID_OFF + (size_t)bi * (2 * DD) + h2] = v;
    }
    __syncthreads();

    // ---- main row sweep: 512 threads x 1 float4 ----
    const float4* trow = (const float4*)(event_time + b * LL);
    const int4*   yrow = (const int4*)  (event_type + b * LL);
    float4* srow = (float4*)(out + SCORES_OFF + (size_t)bi * LL);
    float4* drow = (float4*)(out + TD_OFF     + (size_t)bi * LL);

    const int v  = tid;
    const int j0 = v << 2;

    float4 tj = trow[v];
    int4   ty = yrow[v];

    float4 td;
    td.x = fabsf(tj.x - t_i);
    td.y = fabsf(tj.y - t_i);
    td.z = fabsf(tj.z - t_i);
    td.w = fabsf(tj.w - t_i);

    float4 sd;
    if (j0 + 3 < i) {
        // fully below diagonal: all four live
        float2 px = sh[ty.x], py = sh[ty.y], pz = sh[ty.z], pw = sh[ty.w];
        sd.x = px.x * __expf(px.y * td.x);
        sd.y = py.x * __expf(py.y * td.y);
        sd.z = pz.x * __expf(pz.y * td.z);
        sd.w = pw.x * __expf(pw.y * td.w);
    } else if (j0 >= i) {
        // fully on/above diagonal: all zero
        sd.x = 0.0f; sd.y = 0.0f; sd.z = 0.0f; sd.w = 0.0f;
    } else {
        // boundary float4 (at most one warp per block diverges here)
        sd.x = 0.0f; sd.y = 0.0f; sd.z = 0.0f; sd.w = 0.0f;
        if (j0 + 0 < i) { float2 p = sh[ty.x]; sd.x = p.x * __expf(p.y * td.x); }
        if (j0 + 1 < i) { float2 p = sh[ty.y]; sd.y = p.x * __expf(p.y * td.y); }
        if (j0 + 2 < i) { float2 p = sh[ty.z]; sd.z = p.x * __expf(p.y * td.z); }
        if (j0 + 3 < i) { float2 p = sh[ty.w]; sd.w = p.x * __expf(p.y * td.w); }
    }

    drow[v] = td;
    srow[v] = sd;
}

extern "C" void kernel_launch(void* const* d_in, const int* in_sizes, int n_in,
                              void* d_out, int out_size)
{
    const int*   event_type = (const int*)  d_in[0];
    const float* event_time = (const float*)d_in[1];
    const float* Wt         = (const float*)d_in[2];
    const float* type_table = (const float*)d_in[3];
    const float* w_g        = (const float*)d_in[4];
    const float* b_g        = (const float*)d_in[5];
    const float* w_s        = (const float*)d_in[6];
    const float* b_s        = (const float*)d_in[7];
    const float* w_d        = (const float*)d_in[8];
    const float* b_d        = (const float*)d_in[9];
    float* out = (float*)d_out;

    fused_kernel<<<BB * LL, 512>>>(event_type, event_time, Wt, type_table,
                                   w_g, b_g, w_s, b_s, w_d, b_d, out);
}

// round 5
// speedup vs baseline: 1.7507x; 1.7507x over previous
#include <cuda_runtime.h>
#include <math.h>

#define BB 4
#define LL 2048
#define DD 32
#define TT 21   // NUM_TYPES + 1

// out layout (f32):
//   scores  : [B, L, L]   at offset 0
//   hidden  : [B, L, 2D]  at offset B*L*L
//   t_diff  : [B, L, L]   at offset B*L*L + B*L*2D
#define SCORES_OFF  ((size_t)0)
#define HID_OFF     ((size_t)BB * LL * LL)
#define TD_OFF      (HID_OFF + (size_t)BB * LL * 2 * DD)

// 21x21 pairwise-type tables, packed: (gs, dn) at index ti*TT + tj
__device__ float2 g_tab[TT * TT];

// div_term[h] = 10^(-h/4), hardcoded
__device__ __constant__ float c_divt[16] = {
    1.0f, 0.5623413251903491f, 0.31622776601683794f, 0.17782794100389226f,
    0.1f, 0.05623413251903491f, 0.031622776601683791f, 0.017782794100389228f,
    0.01f, 0.005623413251903491f, 0.0031622776601683794f, 0.0017782794100389228f,
    0.001f, 0.0005623413251903491f, 0.00031622776601683794f, 0.00017782794100389227f
};

// One WARP per (ti, tj) table entry: lane k accumulates emb_j[k]*w[k] + emb_i[k]*w[32+k],
// then 3 butterfly reductions. 441 warps over 112 blocks x 4 warps.
__global__ __launch_bounds__(128)
void tables_kernel(const float* __restrict__ type_table,
                   const float* __restrict__ w_g, const float* __restrict__ b_g,
                   const float* __restrict__ w_s, const float* __restrict__ b_s,
                   const float* __restrict__ w_d, const float* __restrict__ b_d)
{
    const int warp = (blockIdx.x * blockDim.x + threadIdx.x) >> 5;
    const int lane = threadIdx.x & 31;
    if (warp >= TT * TT) return;
    const int ti = warp / TT;
    const int tj = warp - ti * TT;

    const float aj = type_table[tj * DD + lane];
    const float ai = type_table[ti * DD + lane];

    float g = fmaf(aj, w_g[lane], ai * w_g[DD + lane]);
    float s = fmaf(aj, w_s[lane], ai * w_s[DD + lane]);
    float d = fmaf(aj, w_d[lane], ai * w_d[DD + lane]);
#pragma unroll
    for (int off = 16; off > 0; off >>= 1) {
        g += __shfl_xor_sync(0xffffffffu, g, off);
        s += __shfl_xor_sync(0xffffffffu, s, off);
        d += __shfl_xor_sync(0xffffffffu, d, off);
    }
    if (lane == 0) {
        g += *b_g; s += *b_s; d += *b_d;
        float sig = 1.0f / (1.0f + expf(-g));
        float sps = fmaxf(s, 0.0f) + log1pf(expf(-fabsf(s)));
        float spd = fmaxf(d, 0.0f) + log1pf(expf(-fabsf(d)));
        g_tab[warp] = make_float2(sig * sps, -spd);
    }
}

// One block per (b, i) row. 256 threads x 2 float4 per output array.
__global__ __launch_bounds__(256, 8)
void row_kernel(const int*   __restrict__ event_type,
                const float* __restrict__ event_time,
                const float* __restrict__ Wt,
                const float* __restrict__ type_table,
                float* __restrict__ out)
{
    const int bi  = blockIdx.x;          // b * L + i
    const int b   = bi >> 11;
    const int i   = bi & (LL - 1);
    const int tid = threadIdx.x;

    __shared__ float2 sh[TT];            // (gs, dn) for this row's type_i

    const int   tyi = event_type[bi];    // broadcast
    const float t_i = event_time[bi];    // broadcast

    if (tid < TT) sh[tid] = g_tab[tyi * TT + tid];

    // fused hidden_vector row: threads 0..63
    if (tid < 2 * DD) {
        float v;
        if (tid < DD) {
            int h = tid & 15;
            float arg = fmaf((float)i, c_divt[h], t_i * Wt[h]);
            v = (tid < 16) ? sinf(arg) : cosf(arg);
        } else {
            v = type_table[tyi * DD + (tid - DD)];
        }
        out[HID_OFF + (size_t)bi * (2 * DD) + tid] = v;
    }
    __syncthreads();

    const float4* trow = (const float4*)(event_time + b * LL);
    const int4*   yrow = (const int4*)  (event_type + b * LL);
    float4* srow = (float4*)(out + SCORES_OFF + (size_t)bi * LL);
    float4* drow = (float4*)(out + TD_OFF     + (size_t)bi * LL);

#pragma unroll
    for (int c = 0; c < 2; c++) {
        const int v  = tid + c * 256;    // float4 index within the row
        const int j0 = v << 2;

        float4 tj = trow[v];

        float4 td;
        td.x = fabsf(tj.x - t_i);
        td.y = fabsf(tj.y - t_i);
        td.z = fabsf(tj.z - t_i);
        td.w = fabsf(tj.w - t_i);

        float4 sd;
        if (j0 >= i) {
            // fully on/above diagonal: no table lookup, no exp
            sd.x = 0.0f; sd.y = 0.0f; sd.z = 0.0f; sd.w = 0.0f;
        } else {
            int4 ty = yrow[v];
            if (j0 + 3 < i) {
                float2 px = sh[ty.x], py = sh[ty.y], pz = sh[ty.z], pw = sh[ty.w];
                sd.x = px.x * __expf(px.y * td.x);
                sd.y = py.x * __expf(py.y * td.y);
                sd.z = pz.x * __expf(pz.y * td.z);
                sd.w = pw.x * __expf(pw.y * td.w);
            } else {
                // boundary float4 (one warp per block at most)
                sd.x = 0.0f; sd.y = 0.0f; sd.z = 0.0f; sd.w = 0.0f;
                if (j0 + 0 < i) { float2 p = sh[ty.x]; sd.x = p.x * __expf(p.y * td.x); }
                if (j0 + 1 < i) { float2 p = sh[ty.y]; sd.y = p.x * __expf(p.y * td.y); }
                if (j0 + 2 < i) { float2 p = sh[ty.z]; sd.z = p.x * __expf(p.y * td.z); }
                if (j0 + 3 < i) { float2 p = sh[ty.w]; sd.w = p.x * __expf(p.y * td.w); }
            }
        }

        drow[v] = td;
        srow[v] = sd;
    }
}

extern "C" void kernel_launch(void* const* d_in, const int* in_sizes, int n_in,
                              void* d_out, int out_size)
{
    const int*   event_type = (const int*)  d_in[0];
    const float* event_time = (const float*)d_in[1];
    const float* Wt         = (const float*)d_in[2];
    const float* type_table = (const float*)d_in[3];
    const float* w_g        = (const float*)d_in[4];
    const float* b_g        = (const float*)d_in[5];
    const float* w_s        = (const float*)d_in[6];
    const float* b_s        = (const float*)d_in[7];
    const float* w_d        = (const float*)d_in[8];
    const float* b_d        = (const float*)d_in[9];
    float* out = (float*)d_out;

    tables_kernel<<<(TT * TT * 32 + 127) / 128, 128>>>(type_table, w_g, b_g, w_s, b_s, w_d, b_d);
    row_kernel<<<BB * LL, 256>>>(event_type, event_time, Wt, type_table, out);
}